// round 2
// baseline (speedup 1.0000x reference)
#include <cuda_runtime.h>
#include <cstdint>

// FSMN depthwise strided FIR on GB300 — R2.
// Change vs R1: filter taps are NOT cached in per-thread register arrays
// (82 regs!). Each tap is re-loaded from global (L1/L2-resident, coalesced)
// inside the fully-unrolled tap loop. __launch_bounds__(256,4) forces
// <=64 regs -> 4 blocks/SM -> occupancy 50% (was 22%).
//
// Parity decomposition: outputs t0, t0+2, ..., t0+14 (8 same-parity outputs)
// read two DENSE streams with a rotating 8-deep register window:
//   A[u] = x[t0-40+2u]  (taps filt[0..20])
//   B[v] = x[t0+1+2v]   (taps filt[21..40])
// Packed fma.rn.f32x2 halves FMA-pipe instruction count (PTX required;
// ptxas will not auto-fuse).

#define B_ 32
#define T_ 2000
#define DP 256          // d-pairs (float2 lanes)
#define RT 8            // outputs per parity chunk
#define SEG 5           // 16-wide t-bases per block; 2000 = 25*5*16

__device__ __forceinline__ uint64_t f2fma(uint64_t a, uint64_t b, uint64_t c) {
    uint64_t r;
    asm("fma.rn.f32x2 %0, %1, %2, %3;" : "=l"(r) : "l"(a), "l"(b), "l"(c));
    return r;
}

__global__ __launch_bounds__(256, 4)
void fsmn_kernel(const float* __restrict__ x,
                 const float* __restrict__ filt,
                 float* __restrict__ out)
{
    const int dp  = threadIdx.x;      // d-pair index 0..255
    const int b   = blockIdx.y;
    const int seg = blockIdx.x;

    // Per-thread pointer to this channel-pair's filter column.
    const uint64_t* __restrict__ fdp =
        reinterpret_cast<const uint64_t*>(filt) + dp;

    const uint64_t* __restrict__ xb =
        reinterpret_cast<const uint64_t*>(x) + (size_t)b * T_ * DP + dp;
    uint64_t* __restrict__ ob =
        reinterpret_cast<uint64_t*>(out) + (size_t)b * T_ * DP + dp;

    for (int s = 0; s < SEG; ++s) {
        const int tb = (seg * SEG + s) * (2 * RT);
        // Inputs touched by both parity chunks span [tb-40, tb+54].
        const bool fast = (tb >= 40) && (tb + 54 < T_);

#pragma unroll
        for (int par = 0; par < 2; ++par) {
            const int t0 = tb + par;

            uint64_t acc[RT];
#pragma unroll
            for (int r = 0; r < RT; ++r) acc[r] = 0ull;

            uint64_t w[RT];

            // ---------- A stream: taps filt[0..20] over x[t0-40+2u] ----------
            {
                const int tA = t0 - 40;
                if (fast) {
#pragma unroll
                    for (int u = 0; u < RT; ++u)
                        w[u] = xb[(size_t)(tA + 2 * u) * DP];
#pragma unroll
                    for (int c = 0; c < 21; ++c) {
                        const uint64_t tap = fdp[(size_t)c * DP];
#pragma unroll
                        for (int r = 0; r < RT; ++r)
                            acc[r] = f2fma(tap, w[(c + r) & (RT - 1)], acc[r]);
                        if (c < 20)
                            w[c & (RT - 1)] = xb[(size_t)(tA + 2 * (c + RT)) * DP];
                    }
                } else {
#pragma unroll
                    for (int u = 0; u < RT; ++u) {
                        const int ti = tA + 2 * u;
                        w[u] = (ti >= 0 && ti < T_) ? xb[(size_t)ti * DP] : 0ull;
                    }
#pragma unroll
                    for (int c = 0; c < 21; ++c) {
                        const uint64_t tap = fdp[(size_t)c * DP];
#pragma unroll
                        for (int r = 0; r < RT; ++r)
                            acc[r] = f2fma(tap, w[(c + r) & (RT - 1)], acc[r]);
                        if (c < 20) {
                            const int ti = tA + 2 * (c + RT);
                            w[c & (RT - 1)] =
                                (ti >= 0 && ti < T_) ? xb[(size_t)ti * DP] : 0ull;
                        }
                    }
                }
            }

            // ---------- B stream: taps filt[21..40] over x[t0+1+2v] ----------
            {
                const int tB = t0 + 1;
                if (fast) {
#pragma unroll
                    for (int u = 0; u < RT; ++u)
                        w[u] = xb[(size_t)(tB + 2 * u) * DP];
#pragma unroll
                    for (int c = 0; c < 20; ++c) {
                        const uint64_t tap = fdp[(size_t)(21 + c) * DP];
#pragma unroll
                        for (int r = 0; r < RT; ++r)
                            acc[r] = f2fma(tap, w[(c + r) & (RT - 1)], acc[r]);
                        if (c < 19)
                            w[c & (RT - 1)] = xb[(size_t)(tB + 2 * (c + RT)) * DP];
                    }
                } else {
#pragma unroll
                    for (int u = 0; u < RT; ++u) {
                        const int ti = tB + 2 * u;
                        w[u] = (ti >= 0 && ti < T_) ? xb[(size_t)ti * DP] : 0ull;
                    }
#pragma unroll
                    for (int c = 0; c < 20; ++c) {
                        const uint64_t tap = fdp[(size_t)(21 + c) * DP];
#pragma unroll
                        for (int r = 0; r < RT; ++r)
                            acc[r] = f2fma(tap, w[(c + r) & (RT - 1)], acc[r]);
                        if (c < 19) {
                            const int ti = tB + 2 * (c + RT);
                            w[c & (RT - 1)] =
                                (ti >= 0 && ti < T_) ? xb[(size_t)ti * DP] : 0ull;
                        }
                    }
                }
            }

            // ---------- store 8 outputs (always in-bounds: t0+14 <= 1999) ----------
#pragma unroll
            for (int r = 0; r < RT; ++r)
                ob[(size_t)(t0 + 2 * r) * DP] = acc[r];
        }
    }
}

extern "C" void kernel_launch(void* const* d_in, const int* in_sizes, int n_in,
                              void* d_out, int out_size)
{
    const float* x    = (const float*)d_in[0];   // [32, 2000, 512] f32
    const float* filt = (const float*)d_in[1];   // [41, 512] f32
    float* out        = (float*)d_out;           // [32, 2000, 512] f32

    dim3 grid(25, B_);   // 25 t-segments x 32 batch
    fsmn_kernel<<<grid, 256>>>(x, filt, out);
}

// round 3
// speedup vs baseline: 1.4838x; 1.4838x over previous
#include <cuda_runtime.h>
#include <cstdint>

// FSMN depthwise strided FIR on GB300 — R3.
// vs R1 (98.8us): replace rotating 8-deep window (load->use distance ~16 cyc,
// exposed to 234-577 cyc memory latency) with a FLAT 28-deep window whose
// loads are all batched up-front (MLP=28). FMA block then runs fully
// register-resident. Taps are loaded from global through a depth-4 rotating
// prefetch pipeline (L1-resident after first chunk; 32-issue-slot distance
// covers L1 hit latency).
//
// out[b,t,d] = sum_{i=0..19} filt[i,d]*x[b,t-(20-i)*2,d]
//            + filt[20,d]*x[b,t,d]
//            + sum_{j=0..19} filt[21+j,d]*x[b,t+1+2j,d],  zero-padded.
//
// Parity decomposition: 8 same-parity outputs t0+2r read dense streams
//   A[u]=x[t0-40+2u] (u=0..27, taps filt[0..20]),  out r uses A[c+r]
//   B[v]=x[t0+1+2v]  (v=0..26, taps filt[21..40]), out r uses B[c+r]
// Packed fma.rn.f32x2 (PTX-only) halves FMA-pipe instruction count.

#define B_ 32
#define T_ 2000
#define DP 256          // d-pairs (float2 lanes)
#define RT 8            // outputs per parity chunk
#define SEG 5           // 16-wide t-bases per block; 2000 = 25*5*16
#define WA 28           // A-stream window (21 taps + 7)
#define WB 27           // B-stream window (20 taps + 7)

__device__ __forceinline__ uint64_t f2fma(uint64_t a, uint64_t b, uint64_t c) {
    uint64_t r;
    asm("fma.rn.f32x2 %0, %1, %2, %3;" : "=l"(r) : "l"(a), "l"(b), "l"(c));
    return r;
}

__global__ __launch_bounds__(256, 2)
void fsmn_kernel(const float* __restrict__ x,
                 const float* __restrict__ filt,
                 float* __restrict__ out)
{
    const int dp  = threadIdx.x;      // d-pair index 0..255
    const int b   = blockIdx.y;
    const int seg = blockIdx.x;

    const uint64_t* __restrict__ fdp =
        reinterpret_cast<const uint64_t*>(filt) + dp;
    const uint64_t* __restrict__ xb =
        reinterpret_cast<const uint64_t*>(x) + (size_t)b * T_ * DP + dp;
    uint64_t* __restrict__ ob =
        reinterpret_cast<uint64_t*>(out) + (size_t)b * T_ * DP + dp;

    for (int s = 0; s < SEG; ++s) {
        const int tb = (seg * SEG + s) * (2 * RT);
        // Inputs touched by both parity chunks span [tb-40, tb+54].
        const bool fast = (tb >= 40) && (tb + 54 < T_);

#pragma unroll
        for (int par = 0; par < 2; ++par) {
            const int t0 = tb + par;

            uint64_t acc[RT];
#pragma unroll
            for (int r = 0; r < RT; ++r) acc[r] = 0ull;

            uint64_t w[WA];     // reused for both streams
            uint64_t tp[4];     // tap prefetch pipeline

            // ================= A stream: taps filt[0..20] =================
            {
                const int tA = t0 - 40;
                if (fast) {
#pragma unroll
                    for (int u = 0; u < WA; ++u)
                        w[u] = xb[(size_t)(tA + 2 * u) * DP];
                } else {
#pragma unroll
                    for (int u = 0; u < WA; ++u) {
                        const int ti = tA + 2 * u;
                        w[u] = (ti >= 0 && ti < T_) ? xb[(size_t)ti * DP] : 0ull;
                    }
                }
#pragma unroll
                for (int k = 0; k < 4; ++k) tp[k] = fdp[(size_t)k * DP];
#pragma unroll
                for (int c = 0; c < 21; ++c) {
                    const uint64_t tap = tp[c & 3];
                    if (c + 4 < 21) tp[c & 3] = fdp[(size_t)(c + 4) * DP];
#pragma unroll
                    for (int r = 0; r < RT; ++r)
                        acc[r] = f2fma(tap, w[c + r], acc[r]);
                }
            }

            // ================= B stream: taps filt[21..40] =================
            {
                const int tB = t0 + 1;
                if (fast) {
#pragma unroll
                    for (int u = 0; u < WB; ++u)
                        w[u] = xb[(size_t)(tB + 2 * u) * DP];
                } else {
#pragma unroll
                    for (int u = 0; u < WB; ++u) {
                        const int ti = tB + 2 * u;
                        w[u] = (ti >= 0 && ti < T_) ? xb[(size_t)ti * DP] : 0ull;
                    }
                }
#pragma unroll
                for (int k = 0; k < 4; ++k) tp[k] = fdp[(size_t)(21 + k) * DP];
#pragma unroll
                for (int c = 0; c < 20; ++c) {
                    const uint64_t tap = tp[c & 3];
                    if (c + 4 < 20) tp[c & 3] = fdp[(size_t)(21 + c + 4) * DP];
#pragma unroll
                    for (int r = 0; r < RT; ++r)
                        acc[r] = f2fma(tap, w[c + r], acc[r]);
                }
            }

            // ---- store 8 outputs (always in-bounds: t0+14 <= 1999) ----
#pragma unroll
            for (int r = 0; r < RT; ++r)
                ob[(size_t)(t0 + 2 * r) * DP] = acc[r];
        }
    }
}

extern "C" void kernel_launch(void* const* d_in, const int* in_sizes, int n_in,
                              void* d_out, int out_size)
{
    const float* x    = (const float*)d_in[0];   // [32, 2000, 512] f32
    const float* filt = (const float*)d_in[1];   // [41, 512] f32
    float* out        = (float*)d_out;           // [32, 2000, 512] f32

    dim3 grid(25, B_);   // 25 t-segments x 32 batch
    fsmn_kernel<<<grid, 256>>>(x, filt, out);
}

// round 4
// speedup vs baseline: 2.5753x; 1.7356x over previous
#include <cuda_runtime.h>
#include <cstdint>

// FSMN depthwise strided FIR on GB300 — R4.
// x is staged in SHARED MEMORY (LDS latency 29 cyc vs 234-577 global), so the
// rotating register window refills are cheap to hide. Register pressure is
// kept ~100 by splitting the tap set: A-phase (left taps, both parities)
// completes before B-phase (right taps) begins, so only ~21 taps are live
// at any time alongside 16 accumulators.
//
// out[b,t,d] = sum_{i=0..19} filt[i,d]*x[b,t-(20-i)*2,d]
//            + filt[20,d]*x[b,t,d]
//            + sum_{j=0..19} filt[21+j,d]*x[b,t+1+2j,d],  zero-padded.
//
// Block: 256 thr = 32 d-pairs x 8 t-groups; tile TT=128 outputs, smem rows
// [tb-40, tb+167] = 208 x 32 u64 = 53.2 KB (dynamic). 2 blocks/SM.

#define B_   32
#define T_   2000
#define DPAL 256        // d-pairs across all of D
#define DPB  32         // d-pairs per block
#define RT   8          // outputs per parity chunk
#define TT   128        // t-outputs per block (8 groups x 16)
#define ROWS (TT + 80)  // 208 smem rows
#define SMEM_BYTES (ROWS * DPB * 8)

__device__ __forceinline__ uint64_t f2fma(uint64_t a, uint64_t b, uint64_t c) {
    uint64_t r;
    asm("fma.rn.f32x2 %0, %1, %2, %3;" : "=l"(r) : "l"(a), "l"(b), "l"(c));
    return r;
}

__global__ __launch_bounds__(256, 2)
void fsmn_kernel(const float* __restrict__ x,
                 const float* __restrict__ filt,
                 float* __restrict__ out)
{
    extern __shared__ uint64_t sx[];   // [ROWS][DPB]

    const int tid = threadIdx.x;
    const int tb  = blockIdx.x * TT;          // tile base t
    const int dpg = blockIdx.y * DPB;         // d-pair base
    const int b   = blockIdx.z;

    const uint64_t* __restrict__ xg =
        reinterpret_cast<const uint64_t*>(x) + (size_t)b * T_ * DPAL + dpg;
    uint64_t* __restrict__ og =
        reinterpret_cast<uint64_t*>(out) + (size_t)b * T_ * DPAL + dpg;
    const uint64_t* __restrict__ f2 =
        reinterpret_cast<const uint64_t*>(filt) + dpg;

    // ---------------- cooperative fill (zero-padded at edges) ----------------
#pragma unroll
    for (int k = 0; k < (ROWS * DPB) / 256; ++k) {
        const int i   = tid + k * 256;
        const int row = i >> 5;               // / DPB
        const int dpl = i & (DPB - 1);
        const int t   = tb - 40 + row;
        uint64_t v = 0ull;
        if (t >= 0 && t < T_) v = xg[(size_t)t * DPAL + dpl];
        sx[i] = v;
    }
    __syncthreads();

    // ---------------- per-thread compute ----------------
    const int dpl = tid & (DPB - 1);          // 0..31
    const int g   = tid >> 5;                 // 0..7 (16 t each)
    const uint64_t* __restrict__ sxp = sx + dpl;
    const uint64_t* __restrict__ fdp = f2 + dpl;

    uint64_t acc[16];                          // [par*8 + r]
#pragma unroll
    for (int i = 0; i < 16; ++i) acc[i] = 0ull;

    // ======== A phase: left taps filt[0..20], both parities ========
    {
        uint64_t fL[21];
#pragma unroll
        for (int i = 0; i < 21; ++i) fL[i] = fdp[(size_t)i * DPAL];

#pragma unroll
        for (int par = 0; par < 2; ++par) {
            const int rb = g * 16 + par;      // smem row of x[t0-40]
            uint64_t w[RT];
#pragma unroll
            for (int u = 0; u < RT; ++u)
                w[u] = sxp[(rb + 2 * u) * DPB];
#pragma unroll
            for (int c = 0; c < 21; ++c) {
#pragma unroll
                for (int r = 0; r < RT; ++r)
                    acc[par * RT + r] = f2fma(fL[c], w[(c + r) & (RT - 1)],
                                              acc[par * RT + r]);
                if (c < 20)
                    w[c & (RT - 1)] = sxp[(rb + 2 * (c + RT)) * DPB];
            }
        }
    }

    // ======== B phase: right taps filt[21..40], both parities ========
    {
        uint64_t fR[20];
#pragma unroll
        for (int j = 0; j < 20; ++j) fR[j] = fdp[(size_t)(21 + j) * DPAL];

#pragma unroll
        for (int par = 0; par < 2; ++par) {
            const int rb = g * 16 + par + 41; // smem row of x[t0+1]
            uint64_t w[RT];
#pragma unroll
            for (int u = 0; u < RT; ++u)
                w[u] = sxp[(rb + 2 * u) * DPB];
#pragma unroll
            for (int c = 0; c < 20; ++c) {
#pragma unroll
                for (int r = 0; r < RT; ++r)
                    acc[par * RT + r] = f2fma(fR[c], w[(c + r) & (RT - 1)],
                                              acc[par * RT + r]);
                if (c < 19)
                    w[c & (RT - 1)] = sxp[(rb + 2 * (c + RT)) * DPB];
            }
        }
    }

    // ---------------- store 16 outputs (guard last tile) ----------------
#pragma unroll
    for (int par = 0; par < 2; ++par) {
        const int t0 = tb + g * 16 + par;
#pragma unroll
        for (int r = 0; r < RT; ++r) {
            const int t = t0 + 2 * r;
            if (t < T_) og[(size_t)t * DPAL + dpl] = acc[par * RT + r];
        }
    }
}

extern "C" void kernel_launch(void* const* d_in, const int* in_sizes, int n_in,
                              void* d_out, int out_size)
{
    const float* x    = (const float*)d_in[0];   // [32, 2000, 512] f32
    const float* filt = (const float*)d_in[1];   // [41, 512] f32
    float* out        = (float*)d_out;           // [32, 2000, 512] f32

    cudaFuncSetAttribute(fsmn_kernel,
                         cudaFuncAttributeMaxDynamicSharedMemorySize,
                         SMEM_BYTES);

    dim3 grid((T_ + TT - 1) / TT,   // 16 t-tiles (adjacent tiles adjacent in schedule)
              DPAL / DPB,           // 8 d-pair slabs
              B_);                  // 32 batch
    fsmn_kernel<<<grid, 256, SMEM_BYTES>>>(x, filt, out);
}

// round 5
// speedup vs baseline: 2.6651x; 1.0349x over previous
#include <cuda_runtime.h>
#include <cstdint>

// FSMN depthwise strided FIR on GB300 — R5.
// vs R4 (82.7us): each block is persistent over TPB=4 consecutive t-tiles
// with DOUBLE-BUFFERED smem filled by cp.async.cg (LDGSTS): tile i+1 streams
// in while tile i computes. Removes the fill->sync->compute serialization
// that held issue at 40%. Compute structure identical to R4 (known good).
//
// out[b,t,d] = sum_{i=0..19} filt[i,d]*x[b,t-(20-i)*2,d]
//            + filt[20,d]*x[b,t,d]
//            + sum_{j=0..19} filt[21+j,d]*x[b,t+1+2j,d],  zero-padded.

#define B_   32
#define T_   2000
#define DPAL 256        // d-pairs across all of D
#define DPB  32         // d-pairs per block
#define RT   8          // outputs per parity chunk
#define TT   128        // t-outputs per tile
#define TPB  4          // tiles per block (16 tiles total, grid.x = 4)
#define ROWS (TT + 80)  // 208 smem rows per tile
#define STRIDE (ROWS * DPB)            // u64 per buffer
#define SMEM_BYTES (2 * STRIDE * 8)    // 106496 B

__device__ __forceinline__ uint64_t f2fma(uint64_t a, uint64_t b, uint64_t c) {
    uint64_t r;
    asm("fma.rn.f32x2 %0, %1, %2, %3;" : "=l"(r) : "l"(a), "l"(b), "l"(c));
    return r;
}

__device__ __forceinline__ uint32_t smem_u32(const void* p) {
    uint32_t a;
    asm("{ .reg .u64 t; cvta.to.shared.u64 t, %1; cvt.u32.u64 %0, t; }"
        : "=r"(a) : "l"(p));
    return a;
}

__global__ __launch_bounds__(256, 2)
void fsmn_kernel(const float* __restrict__ x,
                 const float* __restrict__ filt,
                 float* __restrict__ out)
{
    extern __shared__ uint64_t sx[];   // [2][ROWS][DPB]

    const int tid = threadIdx.x;
    const int q0  = blockIdx.x * TPB;         // first tile index
    const int dpg = blockIdx.y * DPB;         // d-pair base
    const int b   = blockIdx.z;

    const uint64_t* __restrict__ xg =
        reinterpret_cast<const uint64_t*>(x) + (size_t)b * T_ * DPAL + dpg;
    uint64_t* __restrict__ og =
        reinterpret_cast<uint64_t*>(out) + (size_t)b * T_ * DPAL + dpg;
    const uint64_t* __restrict__ f2 =
        reinterpret_cast<const uint64_t*>(filt) + dpg;

    const uint32_t sbase = smem_u32(sx);

    // -------- cp.async tile prefetch: 3328 16B units, 13 per thread --------
    // unit u: row = u>>4, col16 = u&15 (16B = 2 d-pairs). Out-of-range rows
    // zero-filled via src-size=0.
    auto prefetch = [&](int buf, int qt) {
        const int tb = qt * TT;
        const uint32_t db = sbase + (uint32_t)buf * (STRIDE * 8);
#pragma unroll
        for (int k = 0; k < 13; ++k) {
            const int u   = tid + k * 256;
            const int row = u >> 4;
            const int c16 = u & 15;
            const int t   = tb - 40 + row;
            const char* gp = reinterpret_cast<const char*>(xg + (size_t)t * DPAL)
                             + c16 * 16;
            const uint32_t dst = db + (uint32_t)(row * DPB) * 8 + c16 * 16;
            const int ok = (t >= 0 && t < T_) ? 16 : 0;
            asm volatile("cp.async.cg.shared.global [%0], [%1], 16, %2;"
                         :: "r"(dst), "l"(gp), "r"(ok) : "memory");
        }
        asm volatile("cp.async.commit_group;" ::: "memory");
    };

    const int dpl = tid & (DPB - 1);          // 0..31
    const int g   = tid >> 5;                 // 0..7 (16 t each)
    const uint64_t* __restrict__ fdp = f2 + dpl;

    prefetch(0, q0);

#pragma unroll
    for (int i = 0; i < TPB; ++i) {
        if (i < TPB - 1) {
            prefetch((i + 1) & 1, q0 + i + 1);
            asm volatile("cp.async.wait_group 1;" ::: "memory");
        } else {
            asm volatile("cp.async.wait_group 0;" ::: "memory");
        }
        __syncthreads();

        const int tb = (q0 + i) * TT;
        const uint64_t* __restrict__ sxp = sx + (i & 1) * STRIDE + dpl;

        uint64_t acc[16];                      // [par*8 + r]
#pragma unroll
        for (int z = 0; z < 16; ++z) acc[z] = 0ull;

        // ======== A phase: left taps filt[0..20], both parities ========
        {
            uint64_t fL[21];
#pragma unroll
            for (int c = 0; c < 21; ++c) fL[c] = fdp[(size_t)c * DPAL];
#pragma unroll
            for (int par = 0; par < 2; ++par) {
                const int rb = g * 16 + par;   // smem row of x[t0-40]
                uint64_t w[RT];
#pragma unroll
                for (int u = 0; u < RT; ++u)
                    w[u] = sxp[(rb + 2 * u) * DPB];
#pragma unroll
                for (int c = 0; c < 21; ++c) {
#pragma unroll
                    for (int r = 0; r < RT; ++r)
                        acc[par * RT + r] = f2fma(fL[c], w[(c + r) & (RT - 1)],
                                                  acc[par * RT + r]);
                    if (c < 20)
                        w[c & (RT - 1)] = sxp[(rb + 2 * (c + RT)) * DPB];
                }
            }
        }

        // ======== B phase: right taps filt[21..40], both parities ========
        {
            uint64_t fR[20];
#pragma unroll
            for (int c = 0; c < 20; ++c) fR[c] = fdp[(size_t)(21 + c) * DPAL];
#pragma unroll
            for (int par = 0; par < 2; ++par) {
                const int rb = g * 16 + par + 41; // smem row of x[t0+1]
                uint64_t w[RT];
#pragma unroll
                for (int u = 0; u < RT; ++u)
                    w[u] = sxp[(rb + 2 * u) * DPB];
#pragma unroll
                for (int c = 0; c < 20; ++c) {
#pragma unroll
                    for (int r = 0; r < RT; ++r)
                        acc[par * RT + r] = f2fma(fR[c], w[(c + r) & (RT - 1)],
                                                  acc[par * RT + r]);
                    if (c < 19)
                        w[c & (RT - 1)] = sxp[(rb + 2 * (c + RT)) * DPB];
                }
            }
        }

        // -------- store 16 outputs (guard: last tile reaches t=2047) --------
#pragma unroll
        for (int par = 0; par < 2; ++par) {
            const int t0 = tb + g * 16 + par;
#pragma unroll
            for (int r = 0; r < RT; ++r) {
                const int t = t0 + 2 * r;
                if (t < T_) og[(size_t)t * DPAL + dpl] = acc[par * RT + r];
            }
        }
        __syncthreads();   // protect buf[i&1] before next iteration's prefetch
    }
}

extern "C" void kernel_launch(void* const* d_in, const int* in_sizes, int n_in,
                              void* d_out, int out_size)
{
    const float* x    = (const float*)d_in[0];   // [32, 2000, 512] f32
    const float* filt = (const float*)d_in[1];   // [41, 512] f32
    float* out        = (float*)d_out;           // [32, 2000, 512] f32

    cudaFuncSetAttribute(fsmn_kernel,
                         cudaFuncAttributeMaxDynamicSharedMemorySize,
                         SMEM_BYTES);

    dim3 grid(4,            // 4 tile-groups x TPB=4 tiles -> 16 t-tiles
              DPAL / DPB,   // 8 d-pair slabs
              B_);          // 32 batch
    fsmn_kernel<<<grid, 256, SMEM_BYTES>>>(x, filt, out);
}